// round 3
// baseline (speedup 1.0000x reference)
#include <cuda_runtime.h>

#define B_ 16
#define D_ 16
#define H_ 288
#define W_ 512
#define N_ (H_*W_)   // 147456
#define L_ 17

// persistent scratch (must be re-zeroed every launch: graph replays reuse it)
__device__ float g_sums[B_][L_][D_];
__device__ float g_cnt[B_][L_];
__device__ float g_means[B_][L_][D_];
__device__ float g_w[B_][L_];

// ---------------------------------------------------------------- kernel 0
__global__ void k0_zero(float* out) {
    int t = blockIdx.x * blockDim.x + threadIdx.x;
    int stride = gridDim.x * blockDim.x;
    if (t == 0) out[0] = 0.f;
    float* s = &g_sums[0][0][0];
    for (int i = t; i < B_*L_*D_; i += stride) s[i] = 0.f;
    float* c = &g_cnt[0][0];
    for (int i = t; i < B_*L_; i += stride) c[i] = 0.f;
}

// ---------------------------------------------------------------- kernel 1
// Per-label sums + counts. block = (32 lanes, 4 dim-warps); each thread owns
// 4 dims x 16 labels of packed f32x2 accumulators (registers, no atomics in
// the hot loop). Label 0 (background) is skipped: its mean never contributes.
__global__ void __launch_bounds__(128) k1_sums(const float* __restrict__ emb,
                                               const int* __restrict__ seg) {
    const int b    = blockIdx.y;
    const int lane = threadIdx.x;
    const int y    = threadIdx.y;                  // 0..3 -> dims 4y..4y+3
    const int chunk = N_ / 32;                     // gridDim.x == 32
    const int lo    = blockIdx.x * chunk;

    const float* __restrict__ e    = emb + ((size_t)b * D_ + y * 4) * N_;
    const int* __restrict__   sp   = seg + (size_t)b * N_;

    unsigned long long a01[16], a23[16];
#pragma unroll
    for (int l = 0; l < 16; l++) { a01[l] = 0ull; a23[l] = 0ull; }
    int cnt[16];
#pragma unroll
    for (int l = 0; l < 16; l++) cnt[l] = 0;

    for (int it = 0; it < chunk; it += 32) {
        int n = lo + it + lane;
        int s = sp[n];
        float v0 = e[n];
        float v1 = e[N_ + n];
        float v2 = e[2 * N_ + n];
        float v3 = e[3 * N_ + n];
        unsigned long long v01, v23;
        asm("mov.b64 %0, {%1,%2};" : "=l"(v01) : "f"(v0), "f"(v1));
        asm("mov.b64 %0, {%1,%2};" : "=l"(v23) : "f"(v2), "f"(v3));
#pragma unroll
        for (int l = 1; l <= 16; l++) {
            asm("{\n\t"
                ".reg .pred p;\n\t"
                "setp.eq.s32 p, %2, %3;\n\t"
                "@p add.rn.f32x2 %0, %0, %4;\n\t"
                "@p add.rn.f32x2 %1, %1, %5;\n\t"
                "}"
                : "+l"(a01[l-1]), "+l"(a23[l-1])
                : "r"(s), "r"(l), "l"(v01), "l"(v23));
            cnt[l-1] += (s == l);
        }
    }

    // unpack packed accumulators -> 64 floats, warp butterfly reduce
    float vals[64];
#pragma unroll
    for (int l = 0; l < 16; l++) {
        float f0, f1, f2, f3;
        asm("mov.b64 {%0,%1}, %2;" : "=f"(f0), "=f"(f1) : "l"(a01[l]));
        asm("mov.b64 {%0,%1}, %2;" : "=f"(f2), "=f"(f3) : "l"(a23[l]));
        vals[l*4+0] = f0; vals[l*4+1] = f1; vals[l*4+2] = f2; vals[l*4+3] = f3;
    }
#pragma unroll
    for (int off = 16; off >= 1; off >>= 1) {
#pragma unroll
        for (int i = 0; i < 64; i++)
            vals[i] += __shfl_xor_sync(0xffffffffu, vals[i], off);
    }
    if (lane == 0) {
#pragma unroll
        for (int l = 0; l < 16; l++)
#pragma unroll
            for (int d = 0; d < 4; d++)
                atomicAdd(&g_sums[b][l+1][y*4+d], vals[l*4+d]);
    }
    if (y == 0) {
#pragma unroll
        for (int l = 0; l < 16; l++) {
            int c = cnt[l];
#pragma unroll
            for (int off = 16; off >= 1; off >>= 1)
                c += __shfl_xor_sync(0xffffffffu, c, off);
            if (lane == 0) atomicAdd(&g_cnt[b][l+1], (float)c);
        }
    }
}

// ---------------------------------------------------------------- kernel 2
// Finalize means/weights + pairwise push (distance) term. Single block.
__global__ void k2_mid(float* out) {
    __shared__ int   pres[B_][L_];
    __shared__ float nlsh[B_];
    __shared__ float red[512];
    const int tid = threadIdx.x;

    for (int idx = tid; idx < B_*L_; idx += 512) {
        int b = idx / L_, l = idx % L_;
        pres[b][l] = (l != 0 && g_cnt[b][l] > 0.f) ? 1 : 0;
    }
    __syncthreads();
    if (tid < B_) {
        int nl = 0;
        for (int l = 0; l < L_; l++) nl += pres[tid][l];
        nlsh[tid] = (float)nl;
    }
    __syncthreads();

    for (int idx = tid; idx < B_*L_*D_; idx += 512) {
        int b = idx / (L_*D_);
        int l = (idx / D_) % L_;
        int d = idx % D_;
        float c = fmaxf(g_cnt[b][l], 1.f);
        g_means[b][l][d] = g_sums[b][l][d] / c;
    }
    for (int idx = tid; idx < B_*L_; idx += 512) {
        int b = idx / L_, l = idx % L_;
        float c  = fmaxf(g_cnt[b][l], 1.f);
        float nl = fmaxf(nlsh[b], 1.f);
        g_w[b][l] = pres[b][l] ? (1.f / (c * nl * (float)B_)) : 0.f;
    }
    __syncthreads();   // g_means visible block-wide

    float acc = 0.f;
    for (int idx = tid; idx < B_*L_*L_; idx += 512) {
        int b = idx / (L_*L_);
        int i = (idx / L_) % L_;
        int j = idx % L_;
        if (i != j && pres[b][i] && pres[b][j]) {
            float nl = nlsh[b];
            if (nl > 1.f) {
                float ss = 0.f;
#pragma unroll
                for (int d = 0; d < D_; d++) {
                    float dm = g_means[b][i][d] - g_means[b][j][d];
                    ss = fmaf(dm, dm, ss);
                }
                float dist = sqrtf(ss);
                float p = fmaxf(1.5f - dist, 0.f);
                float denom = fmaxf(nl * (nl - 1.f), 1.f);
                acc += (p * p) / denom * 0.5f / (float)B_;
            }
        }
    }
    red[tid] = acc;
    __syncthreads();
    for (int s = 256; s > 0; s >>= 1) {
        if (tid < s) red[tid] += red[tid + s];
        __syncthreads();
    }
    if (tid == 0) atomicAdd(out, red[0]);
}

// ---------------------------------------------------------------- kernel 3
// Variance (pull) term, pre-weighted so it sums directly into the loss.
__global__ void __launch_bounds__(256) k3_var(const float* __restrict__ emb,
                                              const int* __restrict__ seg,
                                              float* out) {
    const int b = blockIdx.y;
    __shared__ float sm_m[D_][L_];   // [d][l]: stride-17 kills bank pathology
    __shared__ float sm_w[L_];
    __shared__ float wsum[8];
    const int tid = threadIdx.x;

    for (int idx = tid; idx < D_*L_; idx += 256) {
        int d = idx / L_, l = idx % L_;
        sm_m[d][l] = g_means[b][l][d];
    }
    if (tid < L_) sm_w[tid] = g_w[b][tid];
    __syncthreads();

    const int chunk = N_ / 32;       // gridDim.x == 32
    const int lo    = blockIdx.x * chunk;
    const float* __restrict__ e    = emb + (size_t)b * D_ * N_;
    const int* __restrict__   sp   = seg + (size_t)b * N_;

    float acc = 0.f;
    for (int it = tid; it < chunk; it += 256) {
        int n = lo + it;
        int s = sp[n];
        float w = sm_w[s];           // 0 for background / absent labels
        float ss = 0.f;
#pragma unroll
        for (int d = 0; d < D_; d++) {
            float df = e[(size_t)d * N_ + n] - sm_m[d][s];
            ss = fmaf(df, df, ss);
        }
        float nrm = sqrtf(fmaxf(ss, 1e-12f));
        float t = fmaxf(nrm - 0.5f, 0.f);
        acc = fmaf(w, t * t, acc);
    }
#pragma unroll
    for (int off = 16; off >= 1; off >>= 1)
        acc += __shfl_xor_sync(0xffffffffu, acc, off);
    if ((tid & 31) == 0) wsum[tid >> 5] = acc;
    __syncthreads();
    if (tid < 8) {
        float a = wsum[tid];
#pragma unroll
        for (int off = 4; off >= 1; off >>= 1)
            a += __shfl_xor_sync(0xffu, a, off);
        if (tid == 0) atomicAdd(out, a);
    }
}

// ---------------------------------------------------------------- launch
extern "C" void kernel_launch(void* const* d_in, const int* in_sizes, int n_in,
                              void* d_out, int out_size) {
    const float* emb = (const float*)d_in[0];
    const int*   seg = (const int*)d_in[1];
    float*       out = (float*)d_out;

    k0_zero<<<8, 256>>>(out);

    dim3 g1(32, B_), b1(32, 4);
    k1_sums<<<g1, b1>>>(emb, seg);

    k2_mid<<<1, 512>>>(out);

    dim3 g3(32, B_);
    k3_var<<<g3, 256>>>(emb, seg, out);
}

// round 4
// speedup vs baseline: 1.0553x; 1.0553x over previous
#include <cuda_runtime.h>

#define B_ 16
#define D_ 16
#define H_ 288
#define W_ 512
#define N_ (H_*W_)   // 147456
#define L_ 17
#define CH_ 64       // chunks along N for k1/k3

// persistent scratch (re-zeroed every launch: graph replays reuse it)
__device__ float g_sums[B_][L_][D_];
__device__ float g_cnt[B_][L_];
__device__ float g_means[B_][L_][D_];
__device__ float g_w[B_][L_];

// ---------------------------------------------------------------- kernel 0
__global__ void k0_zero(float* out) {
    int t = blockIdx.x * blockDim.x + threadIdx.x;
    int stride = gridDim.x * blockDim.x;
    if (t == 0) out[0] = 0.f;
    float* s = &g_sums[0][0][0];
    for (int i = t; i < B_*L_*D_; i += stride) s[i] = 0.f;
    float* c = &g_cnt[0][0];
    for (int i = t; i < B_*L_; i += stride) c[i] = 0.f;
}

// ---------------------------------------------------------------- kernel 1
// Per-label sums + counts. block = (32 lanes, 4 dim-warps); each thread owns
// 4 dims x 16 labels of packed f32x2 register accumulators. Depth-2 software
// prefetch hides DRAM latency. Label 0 (background) is skipped (never used).
__global__ void __launch_bounds__(128) k1_sums(const float* __restrict__ emb,
                                               const int* __restrict__ seg) {
    const int b    = blockIdx.y;
    const int lane = threadIdx.x;
    const int y    = threadIdx.y;                  // 0..3 -> dims 4y..4y+3
    const int chunk = N_ / CH_;                    // gridDim.x == CH_
    const int lo    = blockIdx.x * chunk;

    const float* __restrict__ e  = emb + ((size_t)b * D_ + y * 4) * N_;
    const int* __restrict__   sp = seg + (size_t)b * N_;

    unsigned long long a01[16], a23[16];
#pragma unroll
    for (int l = 0; l < 16; l++) { a01[l] = 0ull; a23[l] = 0ull; }
    int cnt[16];
#pragma unroll
    for (int l = 0; l < 16; l++) cnt[l] = 0;

    // prefetch pipeline: A = current, B = next, C = next-next
    int   nA = lo + lane;
    int   sA = sp[nA];
    float A0 = e[nA], A1 = e[N_ + nA], A2 = e[2*N_ + nA], A3 = e[3*N_ + nA];
    int   nB = nA + 32;
    int   sB = sp[nB];
    float B0 = e[nB], B1 = e[N_ + nB], B2 = e[2*N_ + nB], B3 = e[3*N_ + nB];

    for (int it = 0; it < chunk; it += 32) {
        // issue prefetch for it+64 before consuming A
        int   nC = (it + 64 < chunk) ? (lo + it + 64 + lane) : (lo + lane);
        int   sC = sp[nC];
        float C0 = e[nC], C1 = e[N_ + nC], C2 = e[2*N_ + nC], C3 = e[3*N_ + nC];

        unsigned long long v01, v23;
        asm("mov.b64 %0, {%1,%2};" : "=l"(v01) : "f"(A0), "f"(A1));
        asm("mov.b64 %0, {%1,%2};" : "=l"(v23) : "f"(A2), "f"(A3));
#pragma unroll
        for (int l = 1; l <= 16; l++) {
            asm("{\n\t"
                ".reg .pred p;\n\t"
                "setp.eq.s32 p, %2, %3;\n\t"
                "@p add.rn.f32x2 %0, %0, %4;\n\t"
                "@p add.rn.f32x2 %1, %1, %5;\n\t"
                "}"
                : "+l"(a01[l-1]), "+l"(a23[l-1])
                : "r"(sA), "r"(l), "l"(v01), "l"(v23));
        }
        if (y == 0) {                      // counts needed once, not 4x
#pragma unroll
            for (int l = 1; l <= 16; l++) cnt[l-1] += (sA == l);
        }
        // rotate pipeline
        sA = sB; A0 = B0; A1 = B1; A2 = B2; A3 = B3;
        sB = sC; B0 = C0; B1 = C1; B2 = C2; B3 = C3;
    }

    // unpack packed accumulators -> 64 floats, warp butterfly reduce
    float vals[64];
#pragma unroll
    for (int l = 0; l < 16; l++) {
        float f0, f1, f2, f3;
        asm("mov.b64 {%0,%1}, %2;" : "=f"(f0), "=f"(f1) : "l"(a01[l]));
        asm("mov.b64 {%0,%1}, %2;" : "=f"(f2), "=f"(f3) : "l"(a23[l]));
        vals[l*4+0] = f0; vals[l*4+1] = f1; vals[l*4+2] = f2; vals[l*4+3] = f3;
    }
#pragma unroll
    for (int off = 16; off >= 1; off >>= 1) {
#pragma unroll
        for (int i = 0; i < 64; i++)
            vals[i] += __shfl_xor_sync(0xffffffffu, vals[i], off);
    }
    if (lane == 0) {
#pragma unroll
        for (int l = 0; l < 16; l++)
#pragma unroll
            for (int d = 0; d < 4; d++)
                atomicAdd(&g_sums[b][l+1][y*4+d], vals[l*4+d]);
    }
    if (y == 0) {
#pragma unroll
        for (int l = 0; l < 16; l++) {
            int c = cnt[l];
#pragma unroll
            for (int off = 16; off >= 1; off >>= 1)
                c += __shfl_xor_sync(0xffffffffu, c, off);
            if (lane == 0) atomicAdd(&g_cnt[b][l+1], (float)c);
        }
    }
}

// ---------------------------------------------------------------- kernel 2
// Finalize means/weights + pairwise push (distance) term. Single block.
__global__ void k2_mid(float* out) {
    __shared__ int   pres[B_][L_];
    __shared__ float nlsh[B_];
    __shared__ float red[512];
    const int tid = threadIdx.x;

    for (int idx = tid; idx < B_*L_; idx += 512) {
        int b = idx / L_, l = idx % L_;
        pres[b][l] = (l != 0 && g_cnt[b][l] > 0.f) ? 1 : 0;
    }
    __syncthreads();
    if (tid < B_) {
        int nl = 0;
        for (int l = 0; l < L_; l++) nl += pres[tid][l];
        nlsh[tid] = (float)nl;
    }
    __syncthreads();

    for (int idx = tid; idx < B_*L_*D_; idx += 512) {
        int b = idx / (L_*D_);
        int l = (idx / D_) % L_;
        int d = idx % D_;
        float c = fmaxf(g_cnt[b][l], 1.f);
        g_means[b][l][d] = g_sums[b][l][d] / c;
    }
    for (int idx = tid; idx < B_*L_; idx += 512) {
        int b = idx / L_, l = idx % L_;
        float c  = fmaxf(g_cnt[b][l], 1.f);
        float nl = fmaxf(nlsh[b], 1.f);
        g_w[b][l] = pres[b][l] ? (1.f / (c * nl * (float)B_)) : 0.f;
    }
    __syncthreads();   // g_means visible block-wide

    float acc = 0.f;
    for (int idx = tid; idx < B_*L_*L_; idx += 512) {
        int b = idx / (L_*L_);
        int i = (idx / L_) % L_;
        int j = idx % L_;
        if (i != j && pres[b][i] && pres[b][j]) {
            float nl = nlsh[b];
            if (nl > 1.f) {
                float ss = 0.f;
#pragma unroll
                for (int d = 0; d < D_; d++) {
                    float dm = g_means[b][i][d] - g_means[b][j][d];
                    ss = fmaf(dm, dm, ss);
                }
                float dist = sqrtf(ss);
                float p = fmaxf(1.5f - dist, 0.f);
                float denom = fmaxf(nl * (nl - 1.f), 1.f);
                acc += (p * p) / denom * 0.5f / (float)B_;
            }
        }
    }
    red[tid] = acc;
    __syncthreads();
    for (int s = 256; s > 0; s >>= 1) {
        if (tid < s) red[tid] += red[tid + s];
        __syncthreads();
    }
    if (tid == 0) atomicAdd(out, red[0]);
}

// ---------------------------------------------------------------- kernel 3
// Variance (pull) term, pre-weighted so it sums directly into the loss.
__global__ void __launch_bounds__(256) k3_var(const float* __restrict__ emb,
                                              const int* __restrict__ seg,
                                              float* out) {
    const int b = blockIdx.y;
    __shared__ float sm_m[D_][L_];   // [d][l]: stride-17 kills bank pathology
    __shared__ float sm_w[L_];
    __shared__ float wsum[8];
    const int tid = threadIdx.x;

    for (int idx = tid; idx < D_*L_; idx += 256) {
        int d = idx / L_, l = idx % L_;
        sm_m[d][l] = g_means[b][l][d];
    }
    if (tid < L_) sm_w[tid] = g_w[b][tid];
    __syncthreads();

    const int chunk = N_ / CH_;      // gridDim.x == CH_
    const int lo    = blockIdx.x * chunk;
    const float* __restrict__ e  = emb + (size_t)b * D_ * N_;
    const int* __restrict__   sp = seg + (size_t)b * N_;

    float acc = 0.f;
    for (int it = tid; it < chunk; it += 256) {
        int n = lo + it;
        int s = sp[n];
        float w = sm_w[s];           // 0 for background / absent labels
        float ss = 0.f;
#pragma unroll
        for (int d = 0; d < D_; d++) {
            float df = e[(size_t)d * N_ + n] - sm_m[d][s];
            ss = fmaf(df, df, ss);
        }
        float nrm = sqrtf(fmaxf(ss, 1e-12f));
        float t = fmaxf(nrm - 0.5f, 0.f);
        acc = fmaf(w, t * t, acc);
    }
#pragma unroll
    for (int off = 16; off >= 1; off >>= 1)
        acc += __shfl_xor_sync(0xffffffffu, acc, off);
    if ((tid & 31) == 0) wsum[tid >> 5] = acc;
    __syncthreads();
    if (tid < 8) {
        float a = wsum[tid];
#pragma unroll
        for (int off = 4; off >= 1; off >>= 1)
            a += __shfl_xor_sync(0xffu, a, off);
        if (tid == 0) atomicAdd(out, a);
    }
}

// ---------------------------------------------------------------- launch
extern "C" void kernel_launch(void* const* d_in, const int* in_sizes, int n_in,
                              void* d_out, int out_size) {
    const float* emb = (const float*)d_in[0];
    const int*   seg = (const int*)d_in[1];
    float*       out = (float*)d_out;

    k0_zero<<<8, 256>>>(out);

    dim3 g1(CH_, B_), b1(32, 4);
    k1_sums<<<g1, b1>>>(emb, seg);

    k2_mid<<<1, 512>>>(out);

    dim3 g3(CH_, B_);
    k3_var<<<g3, 256>>>(emb, seg, out);
}

// round 6
// speedup vs baseline: 1.0558x; 1.0005x over previous
#include <cuda_runtime.h>

#define B_ 16
#define D_ 16
#define H_ 288
#define W_ 512
#define N_ (H_*W_)   // 147456
#define L_ 17
#define CH_ 64       // chunks along N -> chunk = 2304 px

// persistent scratch (re-zeroed every launch: graph replays reuse it)
__device__ float g_sums[B_][L_][D_];
__device__ float g_cnt[B_][L_];
__device__ float g_means[B_][L_][D_];
__device__ float g_w[B_][L_];

// ---------------------------------------------------------------- kernel 0
__global__ void k0_zero(float* out) {
    int t = blockIdx.x * blockDim.x + threadIdx.x;
    int stride = gridDim.x * blockDim.x;
    if (t == 0) out[0] = 0.f;
    float* s = &g_sums[0][0][0];
    for (int i = t; i < B_*L_*D_; i += stride) s[i] = 0.f;
    float* c = &g_cnt[0][0];
    for (int i = t; i < B_*L_; i += stride) c[i] = 0.f;
}

// ---------------------------------------------------------------- kernel 1
// Per-label sums + counts. block = (32 lanes, 4 dim-warps); each thread owns
// 4 dims x 16 labels of packed f32x2 register accumulators.
// Mask is DATA (selp, 4-cyc) feeding unconditional fma.rn.f32x2 — no 13-cyc
// pred-as-guard chains. 4 pixels/thread via float4/int4, depth-1 prefetch.
__global__ void __launch_bounds__(128) k1_sums(const float* __restrict__ emb,
                                               const int* __restrict__ seg) {
    const int b    = blockIdx.y;
    const int lane = threadIdx.x;
    const int y    = threadIdx.y;                  // 0..3 -> dims 4y..4y+3
    const int chunk = N_ / CH_;                    // 2304
    const int lo    = blockIdx.x * chunk;
    const int ITERS = chunk / 128;                 // 18 (128 px per warp-iter)

    const float* __restrict__ e  = emb + ((size_t)b * D_ + y * 4) * N_;
    const int* __restrict__   sp = seg + (size_t)b * N_;

    unsigned long long a01[16], a23[16];
#pragma unroll
    for (int l = 0; l < 16; l++) { a01[l] = 0ull; a23[l] = 0ull; }
    int cnt[16];
#pragma unroll
    for (int l = 0; l < 16; l++) cnt[l] = 0;

    // depth-1 prefetch
    int n0 = lo + lane * 4;
    int4   sA = *(const int4*)(sp + n0);
    float4 A0 = *(const float4*)(e + n0);
    float4 A1 = *(const float4*)(e + N_   + n0);
    float4 A2 = *(const float4*)(e + 2*N_ + n0);
    float4 A3 = *(const float4*)(e + 3*N_ + n0);

    for (int it = 0; it < ITERS; ++it) {
        int nn = (it + 1 < ITERS) ? (lo + (it + 1) * 128 + lane * 4) : n0;
        int4   sB = *(const int4*)(sp + nn);
        float4 B0 = *(const float4*)(e + nn);
        float4 B1 = *(const float4*)(e + N_   + nn);
        float4 B2 = *(const float4*)(e + 2*N_ + nn);
        float4 B3 = *(const float4*)(e + 3*N_ + nn);

#define PX(S, V0, V1, V2, V3)                                                  \
        {                                                                      \
            unsigned long long v01, v23;                                       \
            asm("mov.b64 %0, {%1,%2};" : "=l"(v01) : "f"(V0), "f"(V1));        \
            asm("mov.b64 %0, {%1,%2};" : "=l"(v23) : "f"(V2), "f"(V3));        \
            _Pragma("unroll")                                                  \
            for (int l = 1; l <= 16; l++) {                                    \
                float m;                                                       \
                asm("{ .reg .pred p; setp.eq.s32 p, %1, %2;"                   \
                    " selp.f32 %0, 0f3F800000, 0f00000000, p; }"               \
                    : "=f"(m) : "r"(S), "r"(l));                               \
                unsigned long long mm;                                         \
                asm("mov.b64 %0, {%1,%1};" : "=l"(mm) : "f"(m));               \
                asm("fma.rn.f32x2 %0, %1, %2, %0;"                             \
                    : "+l"(a01[l-1]) : "l"(mm), "l"(v01));                     \
                asm("fma.rn.f32x2 %0, %1, %2, %0;"                             \
                    : "+l"(a23[l-1]) : "l"(mm), "l"(v23));                     \
            }                                                                  \
        }
        PX(sA.x, A0.x, A1.x, A2.x, A3.x);
        PX(sA.y, A0.y, A1.y, A2.y, A3.y);
        PX(sA.z, A0.z, A1.z, A2.z, A3.z);
        PX(sA.w, A0.w, A1.w, A2.w, A3.w);
#undef PX

        // counts: each iteration handled by exactly one warp (rotation)
        if (((it + y) & 3) == 0) {
#pragma unroll
            for (int l = 1; l <= 16; l++)
                cnt[l-1] += (sA.x == l) + (sA.y == l) + (sA.z == l) + (sA.w == l);
        }

        sA = sB; A0 = B0; A1 = B1; A2 = B2; A3 = B3;
    }

    // unpack packed accumulators -> 64 floats, warp butterfly reduce
    float vals[64];
#pragma unroll
    for (int l = 0; l < 16; l++) {
        float f0, f1, f2, f3;
        asm("mov.b64 {%0,%1}, %2;" : "=f"(f0), "=f"(f1) : "l"(a01[l]));
        asm("mov.b64 {%0,%1}, %2;" : "=f"(f2), "=f"(f3) : "l"(a23[l]));
        vals[l*4+0] = f0; vals[l*4+1] = f1; vals[l*4+2] = f2; vals[l*4+3] = f3;
    }
#pragma unroll
    for (int off = 16; off >= 1; off >>= 1) {
#pragma unroll
        for (int i = 0; i < 64; i++)
            vals[i] += __shfl_xor_sync(0xffffffffu, vals[i], off);
    }
    if (lane == 0) {
#pragma unroll
        for (int l = 0; l < 16; l++)
#pragma unroll
            for (int d = 0; d < 4; d++)
                atomicAdd(&g_sums[b][l+1][y*4+d], vals[l*4+d]);
    }
    // every warp commits its rotated count share
#pragma unroll
    for (int l = 0; l < 16; l++) {
        int c = cnt[l];
#pragma unroll
        for (int off = 16; off >= 1; off >>= 1)
            c += __shfl_xor_sync(0xffffffffu, c, off);
        if (lane == 0 && c > 0) atomicAdd(&g_cnt[b][l+1], (float)c);
    }
}

// ---------------------------------------------------------------- kernel 2
// Finalize means/weights + pairwise push (distance) term. Single block.
__global__ void k2_mid(float* out) {
    __shared__ int   pres[B_][L_];
    __shared__ float nlsh[B_];
    __shared__ float red[512];
    const int tid = threadIdx.x;

    for (int idx = tid; idx < B_*L_; idx += 512) {
        int b = idx / L_, l = idx % L_;
        pres[b][l] = (l != 0 && g_cnt[b][l] > 0.f) ? 1 : 0;
    }
    __syncthreads();
    if (tid < B_) {
        int nl = 0;
        for (int l = 0; l < L_; l++) nl += pres[tid][l];
        nlsh[tid] = (float)nl;
    }
    __syncthreads();

    for (int idx = tid; idx < B_*L_*D_; idx += 512) {
        int b = idx / (L_*D_);
        int l = (idx / D_) % L_;
        int d = idx % D_;
        float c = fmaxf(g_cnt[b][l], 1.f);
        g_means[b][l][d] = g_sums[b][l][d] / c;
    }
    for (int idx = tid; idx < B_*L_; idx += 512) {
        int b = idx / L_, l = idx % L_;
        float c  = fmaxf(g_cnt[b][l], 1.f);
        float nl = fmaxf(nlsh[b], 1.f);
        g_w[b][l] = pres[b][l] ? (1.f / (c * nl * (float)B_)) : 0.f;
    }
    __syncthreads();   // g_means visible block-wide

    float acc = 0.f;
    for (int idx = tid; idx < B_*L_*L_; idx += 512) {
        int b = idx / (L_*L_);
        int i = (idx / L_) % L_;
        int j = idx % L_;
        if (i != j && pres[b][i] && pres[b][j]) {
            float nl = nlsh[b];
            if (nl > 1.f) {
                float ss = 0.f;
#pragma unroll
                for (int d = 0; d < D_; d++) {
                    float dm = g_means[b][i][d] - g_means[b][j][d];
                    ss = fmaf(dm, dm, ss);
                }
                float dist = sqrtf(ss);
                float p = fmaxf(1.5f - dist, 0.f);
                float denom = fmaxf(nl * (nl - 1.f), 1.f);
                acc += (p * p) / denom * 0.5f / (float)B_;
            }
        }
    }
    red[tid] = acc;
    __syncthreads();
    for (int s = 256; s > 0; s >>= 1) {
        if (tid < s) red[tid] += red[tid + s];
        __syncthreads();
    }
    if (tid == 0) atomicAdd(out, red[0]);
}

// ---------------------------------------------------------------- kernel 3
// Variance (pull) term, pre-weighted so it sums directly into the loss.
// 4 pixels/thread via float4/int4; block 288 -> exactly 2 iterations.
__global__ void __launch_bounds__(288) k3_var(const float* __restrict__ emb,
                                              const int* __restrict__ seg,
                                              float* out) {
    const int b = blockIdx.y;
    __shared__ float sm_m[D_][L_];   // [d][l]: 17-float stride, conflict-free
    __shared__ float sm_w[L_];
    __shared__ float wsum[16];
    const int tid = threadIdx.x;

    for (int idx = tid; idx < D_*L_; idx += 288) {
        int d = idx / L_, l = idx % L_;
        sm_m[d][l] = g_means[b][l][d];
    }
    if (tid < L_) sm_w[tid] = g_w[b][tid];
    if (tid < 16) wsum[tid] = 0.f;
    __syncthreads();

    const int chunk = N_ / CH_;      // 2304 = 2 * 288 * 4
    const int lo    = blockIdx.x * chunk;
    const float* __restrict__ e  = emb + (size_t)b * D_ * N_;
    const int* __restrict__   sp = seg + (size_t)b * N_;

    float acc = 0.f;
#pragma unroll
    for (int half = 0; half < 2; half++) {
        int n = lo + half * (288 * 4) + tid * 4;
        int4 s4 = *(const int4*)(sp + n);
        float4 v[D_];
#pragma unroll
        for (int d = 0; d < D_; d++)
            v[d] = *(const float4*)(e + (size_t)d * N_ + n);

#define PXV(S, COMP)                                                           \
        {                                                                      \
            int s = (S);                                                       \
            float w = sm_w[s];                                                 \
            float ss = 0.f;                                                    \
            _Pragma("unroll")                                                  \
            for (int d = 0; d < D_; d++) {                                     \
                float df = v[d].COMP - sm_m[d][s];                             \
                ss = fmaf(df, df, ss);                                         \
            }                                                                  \
            float nrm = sqrtf(fmaxf(ss, 1e-12f));                              \
            float t = fmaxf(nrm - 0.5f, 0.f);                                  \
            acc = fmaf(w, t * t, acc);                                         \
        }
        PXV(s4.x, x); PXV(s4.y, y); PXV(s4.z, z); PXV(s4.w, w);
#undef PXV
    }
#pragma unroll
    for (int off = 16; off >= 1; off >>= 1)
        acc += __shfl_xor_sync(0xffffffffu, acc, off);
    if ((tid & 31) == 0) wsum[tid >> 5] = acc;
    __syncthreads();
    if (tid < 16) {
        float a = wsum[tid];
#pragma unroll
        for (int off = 8; off >= 1; off >>= 1)
            a += __shfl_xor_sync(0xffffu, a, off);
        if (tid == 0) atomicAdd(out, a);
    }
}

// ---------------------------------------------------------------- launch
extern "C" void kernel_launch(void* const* d_in, const int* in_sizes, int n_in,
                              void* d_out, int out_size) {
    const float* emb = (const float*)d_in[0];
    const int*   seg = (const int*)d_in[1];
    float*       out = (float*)d_out;

    k0_zero<<<8, 256>>>(out);

    dim3 g1(CH_, B_), b1(32, 4);
    k1_sums<<<g1, b1>>>(emb, seg);

    k2_mid<<<1, 512>>>(out);

    dim3 g3(CH_, B_);
    k3_var<<<g3, 288>>>(emb, seg, out);
}

// round 7
// speedup vs baseline: 1.2156x; 1.1514x over previous
#include <cuda_runtime.h>

#define B_ 16
#define D_ 16
#define H_ 288
#define W_ 512
#define N_ (H_*W_)   // 147456
#define L_ 17
#define CH_ 64       // chunks along N for k3 -> 2304 px/block

// persistent scratch (re-zeroed every launch: graph replays reuse it)
__device__ float g_sums[B_][L_][D_];
__device__ float g_cnt[B_][L_];
__device__ float g_means[B_][L_][D_];
__device__ float g_w[B_][L_];

// ---------------------------------------------------------------- kernel 0
__global__ void k0_zero(float* out) {
    int t = blockIdx.x * blockDim.x + threadIdx.x;
    int stride = gridDim.x * blockDim.x;
    if (t == 0) out[0] = 0.f;
    float* s = &g_sums[0][0][0];
    for (int i = t; i < B_*L_*D_; i += stride) s[i] = 0.f;
    float* c = &g_cnt[0][0];
    for (int i = t; i < B_*L_; i += stride) c[i] = 0.f;
}

// ---------------------------------------------------------------- kernel 1
// Per-label sums + counts via per-THREAD indexed smem accumulators.
// Block = (32 lanes, 8 warps); warp w owns dims 2w and 2w+1. Each thread has
// a private smem region acc[w][lane][17*2] -> per pixel just LDS+FADD+STS
// indexed by the label (no 16-label predication loop, no atomics, no syncs).
// Counts: rotating warp (it&7)==w does register predicated counting.
__global__ void __launch_bounds__(256) k1_sums(const float* __restrict__ emb,
                                               const int* __restrict__ seg) {
    __shared__ float acc[8][32][34];               // [warp][lane][s*2+d] 34KB

    const int b    = blockIdx.y;
    const int lane = threadIdx.x;
    const int w    = threadIdx.y;                  // dims 2w, 2w+1
    const int chunk = N_ / 32;                     // gridDim.x == 32 -> 4608
    const int lo    = blockIdx.x * chunk;
    const int ITERS = chunk / 128;                 // 36 (128 px per iter)

    float* __restrict__ accw = &acc[w][lane][0];   // private: no sync needed
#pragma unroll
    for (int i = 0; i < 34; i++) accw[i] = 0.f;

    const float* __restrict__ e0 = emb + ((size_t)b * D_ + 2 * w) * N_;
    const float* __restrict__ e1 = e0 + N_;
    const int*   __restrict__ sp = seg + (size_t)b * N_;

    int cnt[16];
#pragma unroll
    for (int l = 0; l < 16; l++) cnt[l] = 0;

    // depth-1 prefetch
    int n0 = lo + lane * 4;
    int4   sA = *(const int4*)(sp + n0);
    float4 A0 = *(const float4*)(e0 + n0);
    float4 A1 = *(const float4*)(e1 + n0);

    for (int it = 0; it < ITERS; ++it) {
        int nn = (it + 1 < ITERS) ? (lo + (it + 1) * 128 + lane * 4) : n0;
        int4   sB = *(const int4*)(sp + nn);
        float4 B0 = *(const float4*)(e0 + nn);
        float4 B1 = *(const float4*)(e1 + nn);

        // indexed accumulate: 4 pixels, 2 dims each
        { float* p = accw + (sA.x << 1); p[0] += A0.x; p[1] += A1.x; }
        { float* p = accw + (sA.y << 1); p[0] += A0.y; p[1] += A1.y; }
        { float* p = accw + (sA.z << 1); p[0] += A0.z; p[1] += A1.z; }
        { float* p = accw + (sA.w << 1); p[0] += A0.w; p[1] += A1.w; }

        // rotating count warp: every pixel counted exactly once per block
        if (((it - w) & 7) == 0) {
#pragma unroll
            for (int l = 1; l <= 16; l++)
                cnt[l-1] += (sA.x == l) + (sA.y == l) + (sA.z == l) + (sA.w == l);
        }

        sA = sB; A0 = B0; A1 = B1;
    }

    // reduce each thread's private sums across the warp, commit via atomics
#pragma unroll
    for (int s = 1; s < L_; s++) {
        float a0 = accw[s * 2];
        float a1 = accw[s * 2 + 1];
#pragma unroll
        for (int off = 16; off >= 1; off >>= 1) {
            a0 += __shfl_xor_sync(0xffffffffu, a0, off);
            a1 += __shfl_xor_sync(0xffffffffu, a1, off);
        }
        if (lane == 0) {
            atomicAdd(&g_sums[b][s][2 * w],     a0);
            atomicAdd(&g_sums[b][s][2 * w + 1], a1);
        }
    }
#pragma unroll
    for (int l = 0; l < 16; l++) {
        int c = cnt[l];
#pragma unroll
        for (int off = 16; off >= 1; off >>= 1)
            c += __shfl_xor_sync(0xffffffffu, c, off);
        if (lane == 0 && c > 0) atomicAdd(&g_cnt[b][l+1], (float)c);
    }
}

// ---------------------------------------------------------------- kernel 2
// Finalize means/weights + pairwise push (distance) term. Single block.
__global__ void k2_mid(float* out) {
    __shared__ int   pres[B_][L_];
    __shared__ float nlsh[B_];
    __shared__ float red[512];
    const int tid = threadIdx.x;

    for (int idx = tid; idx < B_*L_; idx += 512) {
        int b = idx / L_, l = idx % L_;
        pres[b][l] = (l != 0 && g_cnt[b][l] > 0.f) ? 1 : 0;
    }
    __syncthreads();
    if (tid < B_) {
        int nl = 0;
        for (int l = 0; l < L_; l++) nl += pres[tid][l];
        nlsh[tid] = (float)nl;
    }
    __syncthreads();

    for (int idx = tid; idx < B_*L_*D_; idx += 512) {
        int b = idx / (L_*D_);
        int l = (idx / D_) % L_;
        int d = idx % D_;
        float c = fmaxf(g_cnt[b][l], 1.f);
        g_means[b][l][d] = g_sums[b][l][d] / c;
    }
    for (int idx = tid; idx < B_*L_; idx += 512) {
        int b = idx / L_, l = idx % L_;
        float c  = fmaxf(g_cnt[b][l], 1.f);
        float nl = fmaxf(nlsh[b], 1.f);
        g_w[b][l] = pres[b][l] ? (1.f / (c * nl * (float)B_)) : 0.f;
    }
    __syncthreads();   // g_means visible block-wide

    float acc = 0.f;
    for (int idx = tid; idx < B_*L_*L_; idx += 512) {
        int b = idx / (L_*L_);
        int i = (idx / L_) % L_;
        int j = idx % L_;
        if (i != j && pres[b][i] && pres[b][j]) {
            float nl = nlsh[b];
            if (nl > 1.f) {
                float ss = 0.f;
#pragma unroll
                for (int d = 0; d < D_; d++) {
                    float dm = g_means[b][i][d] - g_means[b][j][d];
                    ss = fmaf(dm, dm, ss);
                }
                float dist = sqrtf(ss);
                float p = fmaxf(1.5f - dist, 0.f);
                float denom = fmaxf(nl * (nl - 1.f), 1.f);
                acc += (p * p) / denom * 0.5f / (float)B_;
            }
        }
    }
    red[tid] = acc;
    __syncthreads();
    for (int s = 256; s > 0; s >>= 1) {
        if (tid < s) red[tid] += red[tid + s];
        __syncthreads();
    }
    if (tid == 0) atomicAdd(out, red[0]);
}

// ---------------------------------------------------------------- kernel 3
// Variance (pull) term, pre-weighted so it sums directly into the loss.
// 4 pixels/thread via float4/int4; block 288 -> exactly 2 iterations.
__global__ void __launch_bounds__(288) k3_var(const float* __restrict__ emb,
                                              const int* __restrict__ seg,
                                              float* out) {
    const int b = blockIdx.y;
    __shared__ float sm_m[D_][L_];   // [d][l]: 17-float stride, conflict-free
    __shared__ float sm_w[L_];
    __shared__ float wsum[16];
    const int tid = threadIdx.x;

    for (int idx = tid; idx < D_*L_; idx += 288) {
        int d = idx / L_, l = idx % L_;
        sm_m[d][l] = g_means[b][l][d];
    }
    if (tid < L_) sm_w[tid] = g_w[b][tid];
    if (tid < 16) wsum[tid] = 0.f;
    __syncthreads();

    const int chunk = N_ / CH_;      // 2304 = 2 * 288 * 4
    const int lo    = blockIdx.x * chunk;
    const float* __restrict__ e  = emb + (size_t)b * D_ * N_;
    const int* __restrict__   sp = seg + (size_t)b * N_;

    float acc = 0.f;
#pragma unroll
    for (int half = 0; half < 2; half++) {
        int n = lo + half * (288 * 4) + tid * 4;
        int4 s4 = *(const int4*)(sp + n);
        float4 v[D_];
#pragma unroll
        for (int d = 0; d < D_; d++)
            v[d] = *(const float4*)(e + (size_t)d * N_ + n);

#define PXV(S, COMP)                                                           \
        {                                                                      \
            int s = (S);                                                       \
            float w = sm_w[s];                                                 \
            float ss = 0.f;                                                    \
            _Pragma("unroll")                                                  \
            for (int d = 0; d < D_; d++) {                                     \
                float df = v[d].COMP - sm_m[d][s];                             \
                ss = fmaf(df, df, ss);                                         \
            }                                                                  \
            float nrm = sqrtf(fmaxf(ss, 1e-12f));                              \
            float t = fmaxf(nrm - 0.5f, 0.f);                                  \
            acc = fmaf(w, t * t, acc);                                         \
        }
        PXV(s4.x, x); PXV(s4.y, y); PXV(s4.z, z); PXV(s4.w, w);
#undef PXV
    }
#pragma unroll
    for (int off = 16; off >= 1; off >>= 1)
        acc += __shfl_xor_sync(0xffffffffu, acc, off);
    if ((tid & 31) == 0) wsum[tid >> 5] = acc;
    __syncthreads();
    if (tid < 16) {
        float a = wsum[tid];
#pragma unroll
        for (int off = 8; off >= 1; off >>= 1)
            a += __shfl_xor_sync(0xffffu, a, off);
        if (tid == 0) atomicAdd(out, a);
    }
}

// ---------------------------------------------------------------- launch
extern "C" void kernel_launch(void* const* d_in, const int* in_sizes, int n_in,
                              void* d_out, int out_size) {
    const float* emb = (const float*)d_in[0];
    const int*   seg = (const int*)d_in[1];
    float*       out = (float*)d_out;

    k0_zero<<<8, 256>>>(out);

    dim3 g1(32, B_), b1(32, 8);
    k1_sums<<<g1, b1>>>(emb, seg);

    k2_mid<<<1, 512>>>(out);

    dim3 g3(CH_, B_);
    k3_var<<<g3, 288>>>(emb, seg, out);
}

// round 9
// speedup vs baseline: 1.4307x; 1.1769x over previous
#include <cuda_runtime.h>

#define B_ 16
#define D_ 16
#define H_ 288
#define W_ 512
#define N_ (H_*W_)   // 147456
#define L_ 17
#define CH_ 64       // chunks along N for k3 -> 2304 px/block

// persistent scratch (re-zeroed every launch: graph replays reuse it)
__device__ float g_sums[B_][L_][D_];
__device__ float g_cnt[B_][L_];
__device__ float g_means[B_][L_][D_];
__device__ float g_w[B_][L_];

// ---------------------------------------------------------------- kernel 0
__global__ void k0_zero(float* out) {
    int t = blockIdx.x * blockDim.x + threadIdx.x;
    int stride = gridDim.x * blockDim.x;
    if (t == 0) out[0] = 0.f;
    float* s = &g_sums[0][0][0];
    for (int i = t; i < B_*L_*D_; i += stride) s[i] = 0.f;
    float* c = &g_cnt[0][0];
    for (int i = t; i < B_*L_; i += stride) c[i] = 0.f;
}

// ---------------------------------------------------------------- kernel 1
// Per-label sums + counts via per-THREAD indexed smem accumulators.
// Block = (32 lanes, 8 warps); warp w owns dims 2w, 2w+1.
// 8 pixels/thread/iter -> 6 front-batched LDG.128 + depth-1 prefetch
// (~48 lines in flight per warp) to fix the DRAM-latency bound.
// Two split accumulator arrays (stride 17 -> conflict-light, and two
// independent alias chains, one per dim).
__global__ void __launch_bounds__(256) k1_sums(const float* __restrict__ emb,
                                               const int* __restrict__ seg) {
    __shared__ float ac0[8][32][17];   // [warp][lane][label] dim 2w
    __shared__ float ac1[8][32][17];   // [warp][lane][label] dim 2w+1

    const int b    = blockIdx.y;
    const int lane = threadIdx.x;
    const int w    = threadIdx.y;
    const int chunk = N_ / 32;                     // gridDim.x == 32 -> 4608
    const int lo    = blockIdx.x * chunk;
    const int ITERS = chunk / 256;                 // 18 (256 px per warp-iter)

    float* __restrict__ a0 = &ac0[w][lane][0];     // thread-private
    float* __restrict__ a1 = &ac1[w][lane][0];
#pragma unroll
    for (int i = 0; i < 17; i++) { a0[i] = 0.f; a1[i] = 0.f; }

    const float* __restrict__ e0 = emb + ((size_t)b * D_ + 2 * w) * N_;
    const float* __restrict__ e1 = e0 + N_;
    const int*   __restrict__ sp = seg + (size_t)b * N_;

    int cnt[16];
#pragma unroll
    for (int l = 0; l < 16; l++) cnt[l] = 0;

    // depth-1 prefetch: 6 LDG.128 per stage, two dense 128-px groups
    int nA = lo + lane * 4;
    int4   sAx = *(const int4*)(sp + nA);
    int4   sAy = *(const int4*)(sp + nA + 128);
    float4 pA0 = *(const float4*)(e0 + nA);
    float4 pA1 = *(const float4*)(e0 + nA + 128);
    float4 qA0 = *(const float4*)(e1 + nA);
    float4 qA1 = *(const float4*)(e1 + nA + 128);

    for (int it = 0; it < ITERS; ++it) {
        int nn = (it + 1 < ITERS) ? (lo + (it + 1) * 256 + lane * 4) : nA;
        int4   sBx = *(const int4*)(sp + nn);
        int4   sBy = *(const int4*)(sp + nn + 128);
        float4 pB0 = *(const float4*)(e0 + nn);
        float4 pB1 = *(const float4*)(e0 + nn + 128);
        float4 qB0 = *(const float4*)(e1 + nn);
        float4 qB1 = *(const float4*)(e1 + nn + 128);

        // two independent indexed-accumulate chains (dim0 / dim1)
        a0[sAx.x] += pA0.x;  a1[sAx.x] += qA0.x;
        a0[sAx.y] += pA0.y;  a1[sAx.y] += qA0.y;
        a0[sAx.z] += pA0.z;  a1[sAx.z] += qA0.z;
        a0[sAx.w] += pA0.w;  a1[sAx.w] += qA0.w;
        a0[sAy.x] += pA1.x;  a1[sAy.x] += qA1.x;
        a0[sAy.y] += pA1.y;  a1[sAy.y] += qA1.y;
        a0[sAy.z] += pA1.z;  a1[sAy.z] += qA1.z;
        a0[sAy.w] += pA1.w;  a1[sAy.w] += qA1.w;

        // rotating count warp: every iteration counted exactly once
        if (((it - w) & 7) == 0) {
#pragma unroll
            for (int l = 1; l <= 16; l++)
                cnt[l-1] += (sAx.x == l) + (sAx.y == l) + (sAx.z == l) + (sAx.w == l)
                          + (sAy.x == l) + (sAy.y == l) + (sAy.z == l) + (sAy.w == l);
        }

        sAx = sBx; sAy = sBy;
        pA0 = pB0; pA1 = pB1; qA0 = qB0; qA1 = qB1;
    }

    // reduce each thread's private sums across the warp, commit via atomics
#pragma unroll
    for (int s = 1; s < L_; s++) {
        float v0 = a0[s];
        float v1 = a1[s];
#pragma unroll
        for (int off = 16; off >= 1; off >>= 1) {
            v0 += __shfl_xor_sync(0xffffffffu, v0, off);
            v1 += __shfl_xor_sync(0xffffffffu, v1, off);
        }
        if (lane == 0) {
            atomicAdd(&g_sums[b][s][2 * w],     v0);
            atomicAdd(&g_sums[b][s][2 * w + 1], v1);
        }
    }
#pragma unroll
    for (int l = 0; l < 16; l++) {
        int c = cnt[l];
#pragma unroll
        for (int off = 16; off >= 1; off >>= 1)
            c += __shfl_xor_sync(0xffffffffu, c, off);
        if (lane == 0 && c > 0) atomicAdd(&g_cnt[b][l+1], (float)c);
    }
}

// ---------------------------------------------------------------- kernel 2
// Finalize means/weights + pairwise push (distance) term. Single block.
__global__ void k2_mid(float* out) {
    __shared__ int   pres[B_][L_];
    __shared__ float nlsh[B_];
    __shared__ float red[512];
    const int tid = threadIdx.x;

    for (int idx = tid; idx < B_*L_; idx += 512) {
        int b = idx / L_, l = idx % L_;
        pres[b][l] = (l != 0 && g_cnt[b][l] > 0.f) ? 1 : 0;
    }
    __syncthreads();
    if (tid < B_) {
        int nl = 0;
        for (int l = 0; l < L_; l++) nl += pres[tid][l];
        nlsh[tid] = (float)nl;
    }
    __syncthreads();

    for (int idx = tid; idx < B_*L_*D_; idx += 512) {
        int b = idx / (L_*D_);
        int l = (idx / D_) % L_;
        int d = idx % D_;
        float c = fmaxf(g_cnt[b][l], 1.f);
        g_means[b][l][d] = g_sums[b][l][d] / c;
    }
    for (int idx = tid; idx < B_*L_; idx += 512) {
        int b = idx / L_, l = idx % L_;
        float c  = fmaxf(g_cnt[b][l], 1.f);
        float nl = fmaxf(nlsh[b], 1.f);
        g_w[b][l] = pres[b][l] ? (1.f / (c * nl * (float)B_)) : 0.f;
    }
    __syncthreads();   // g_means visible block-wide

    float acc = 0.f;
    for (int idx = tid; idx < B_*L_*L_; idx += 512) {
        int b = idx / (L_*L_);
        int i = (idx / L_) % L_;
        int j = idx % L_;
        if (i != j && pres[b][i] && pres[b][j]) {
            float nl = nlsh[b];
            if (nl > 1.f) {
                float ss = 0.f;
#pragma unroll
                for (int d = 0; d < D_; d++) {
                    float dm = g_means[b][i][d] - g_means[b][j][d];
                    ss = fmaf(dm, dm, ss);
                }
                float dist = sqrtf(ss);
                float p = fmaxf(1.5f - dist, 0.f);
                float denom = fmaxf(nl * (nl - 1.f), 1.f);
                acc += (p * p) / denom * 0.5f / (float)B_;
            }
        }
    }
    red[tid] = acc;
    __syncthreads();
    for (int s = 256; s > 0; s >>= 1) {
        if (tid < s) red[tid] += red[tid + s];
        __syncthreads();
    }
    if (tid == 0) atomicAdd(out, red[0]);
}

// ---------------------------------------------------------------- kernel 3
// Variance (pull) term, pre-weighted so it sums directly into the loss.
// 4 pixels/thread via float4/int4; block 288 -> exactly 2 iterations.
__global__ void __launch_bounds__(288) k3_var(const float* __restrict__ emb,
                                              const int* __restrict__ seg,
                                              float* out) {
    const int b = blockIdx.y;
    __shared__ float sm_m[D_][L_];   // [d][l]: 17-float stride, conflict-free
    __shared__ float sm_w[L_];
    __shared__ float wsum[16];
    const int tid = threadIdx.x;

    for (int idx = tid; idx < D_*L_; idx += 288) {
        int d = idx / L_, l = idx % L_;
        sm_m[d][l] = g_means[b][l][d];
    }
    if (tid < L_) sm_w[tid] = g_w[b][tid];
    if (tid < 16) wsum[tid] = 0.f;
    __syncthreads();

    const int chunk = N_ / CH_;      // 2304 = 2 * 288 * 4
    const int lo    = blockIdx.x * chunk;
    const float* __restrict__ e  = emb + (size_t)b * D_ * N_;
    const int* __restrict__   sp = seg + (size_t)b * N_;

    float acc = 0.f;
#pragma unroll
    for (int half = 0; half < 2; half++) {
        int n = lo + half * (288 * 4) + tid * 4;
        int4 s4 = *(const int4*)(sp + n);
        float4 v[D_];
#pragma unroll
        for (int d = 0; d < D_; d++)
            v[d] = *(const float4*)(e + (size_t)d * N_ + n);

#define PXV(S, COMP)                                                           \
        {                                                                      \
            int s = (S);                                                       \
            float w = sm_w[s];                                                 \
            float ss = 0.f;                                                    \
            _Pragma("unroll")                                                  \
            for (int d = 0; d < D_; d++) {                                     \
                float df = v[d].COMP - sm_m[d][s];                             \
                ss = fmaf(df, df, ss);                                         \
            }                                                                  \
            float nrm = sqrtf(fmaxf(ss, 1e-12f));                              \
            float t = fmaxf(nrm - 0.5f, 0.f);                                  \
            acc = fmaf(w, t * t, acc);                                         \
        }
        PXV(s4.x, x); PXV(s4.y, y); PXV(s4.z, z); PXV(s4.w, w);
#undef PXV
    }
#pragma unroll
    for (int off = 16; off >= 1; off >>= 1)
        acc += __shfl_xor_sync(0xffffffffu, acc, off);
    if ((tid & 31) == 0) wsum[tid >> 5] = acc;
    __syncthreads();
    if (tid < 16) {
        float a = wsum[tid];
#pragma unroll
        for (int off = 8; off >= 1; off >>= 1)
            a += __shfl_xor_sync(0xffffu, a, off);
        if (tid == 0) atomicAdd(out, a);
    }
}

// ---------------------------------------------------------------- launch
extern "C" void kernel_launch(void* const* d_in, const int* in_sizes, int n_in,
                              void* d_out, int out_size) {
    const float* emb = (const float*)d_in[0];
    const int*   seg = (const int*)d_in[1];
    float*       out = (float*)d_out;

    k0_zero<<<8, 256>>>(out);

    dim3 g1(32, B_), b1(32, 8);
    k1_sums<<<g1, b1>>>(emb, seg);

    k2_mid<<<1, 512>>>(out);

    dim3 g3(CH_, B_);
    k3_var<<<g3, 288>>>(emb, seg, out);
}